// round 1
// baseline (speedup 1.0000x reference)
#include <cuda_runtime.h>
#include <cstdint>

#define LN_EPS 1e-5f
#define NEG_SLOPE 0.2f

// ---------------- scratch (no allocations allowed) ----------------
__device__ float g_z1[2048 * 128];   // x@W1^T + b1
__device__ float g_h2[2048 * 64];    // after LN2+leaky
__device__ float g_h3[2048 * 32];    // after LN3+leaky
__device__ float g_M [2048 * 80];    // h3 @ T
__device__ float g_ob[2048 * 5];     // pairwise accumulators

// ---------------- f32x2 helpers ----------------
__device__ __forceinline__ unsigned long long f32x2_fma(unsigned long long a,
                                                        unsigned long long b,
                                                        unsigned long long c) {
    unsigned long long d;
    asm("fma.rn.f32x2 %0, %1, %2, %3;" : "=l"(d) : "l"(a), "l"(b), "l"(c));
    return d;
}
__device__ __forceinline__ unsigned long long f32x2_add(unsigned long long a,
                                                        unsigned long long b) {
    unsigned long long d;
    asm("add.rn.f32x2 %0, %1, %2;" : "=l"(d) : "l"(a), "l"(b));
    return d;
}
__device__ __forceinline__ float hadd2(unsigned long long a) {
    union { unsigned long long u; float2 f; } c; c.u = a;
    return c.f.x + c.f.y;
}
__device__ __forceinline__ float warp_sum32(float v) {
    v += __shfl_xor_sync(0xffffffffu, v, 16);
    v += __shfl_xor_sync(0xffffffffu, v, 8);
    v += __shfl_xor_sync(0xffffffffu, v, 4);
    v += __shfl_xor_sync(0xffffffffu, v, 2);
    v += __shfl_xor_sync(0xffffffffu, v, 1);
    return v;
}
__device__ __forceinline__ float leaky(float v) {
    return v >= 0.0f ? v : NEG_SLOPE * v;
}

// =====================================================================
// Kernel 1: z1 = x @ W1^T + b1.   M=2048, N=128, K=1024.
// Tile 32x64, BK=32, 128 threads (8x16), thread tile 4x4, packed-k f32x2.
// grid (64, 2)
// =====================================================================
__global__ __launch_bounds__(128) void gemm1_kernel(
    const float* __restrict__ x, const float* __restrict__ W1,
    const float* __restrict__ b1) {
    __shared__ unsigned long long xs[16 * 32];   // [kp][row]
    __shared__ unsigned long long ws[16 * 64];   // [kp][col]

    const int t  = threadIdx.x;
    const int tx = t & 15;          // col group
    const int ty = t >> 4;          // row group
    const int i0 = blockIdx.x * 32;
    const int j0 = blockIdx.y * 64;

    unsigned long long acc[4][4];
#pragma unroll
    for (int r = 0; r < 4; r++)
#pragma unroll
        for (int c = 0; c < 4; c++) acc[r][c] = 0ULL;

    for (int kc = 0; kc < 1024; kc += 32) {
        // load x tile: 32 rows x 32 k = 256 float4, 2 per thread
#pragma unroll
        for (int u = 0; u < 2; u++) {
            int fi  = t + 128 * u;
            int row = fi >> 3;
            int kq  = fi & 7;
            float4 v = *reinterpret_cast<const float4*>(
                &x[(size_t)(i0 + row) * 1024 + kc + kq * 4]);
            union { float2 f; unsigned long long u; } p0, p1;
            p0.f = make_float2(v.x, v.y);
            p1.f = make_float2(v.z, v.w);
            xs[(2 * kq) * 32 + row]     = p0.u;
            xs[(2 * kq + 1) * 32 + row] = p1.u;
        }
        // load W tile: 64 cols x 32 k = 512 float4, 4 per thread
#pragma unroll
        for (int u = 0; u < 4; u++) {
            int fi   = t + 128 * u;
            int wrow = fi >> 3;
            int kq   = fi & 7;
            float4 v = *reinterpret_cast<const float4*>(
                &W1[(size_t)(j0 + wrow) * 1024 + kc + kq * 4]);
            union { float2 f; unsigned long long u; } p0, p1;
            p0.f = make_float2(v.x, v.y);
            p1.f = make_float2(v.z, v.w);
            ws[(2 * kq) * 64 + wrow]     = p0.u;
            ws[(2 * kq + 1) * 64 + wrow] = p1.u;
        }
        __syncthreads();

#pragma unroll
        for (int kp = 0; kp < 16; kp++) {
            unsigned long long a2[4], b2[4];
#pragma unroll
            for (int r = 0; r < 4; r++) a2[r] = xs[kp * 32 + ty + 8 * r];
#pragma unroll
            for (int c = 0; c < 4; c++) b2[c] = ws[kp * 64 + tx + 16 * c];
#pragma unroll
            for (int r = 0; r < 4; r++)
#pragma unroll
                for (int c = 0; c < 4; c++)
                    acc[r][c] = f32x2_fma(a2[r], b2[c], acc[r][c]);
        }
        __syncthreads();
    }

    float bias[4];
#pragma unroll
    for (int c = 0; c < 4; c++) bias[c] = b1[j0 + tx + 16 * c];
#pragma unroll
    for (int r = 0; r < 4; r++) {
        int row = i0 + ty + 8 * r;
#pragma unroll
        for (int c = 0; c < 4; c++) {
            int col = j0 + tx + 16 * c;
            g_z1[(size_t)row * 128 + col] = hadd2(acc[r][c]) + bias[c];
        }
    }
}

// =====================================================================
// Kernel 2a: h1 = leaky(LN(z1)) ; z2 = h1@W2^T + b2 ; h2 = leaky(LN(z2))
// one warp per row, 16 warps/block, grid 128
// =====================================================================
__global__ __launch_bounds__(512) void enc2a_kernel(
    const float* __restrict__ g1, const float* __restrict__ be1,
    const float* __restrict__ W2, const float* __restrict__ b2,
    const float* __restrict__ g2, const float* __restrict__ be2) {
    __shared__ float w2t[128 * 64];      // [k][c]
    __shared__ float h1s[16][128];

    const int t = threadIdx.x;
    // load W2 transposed: W2 is [64][128] row-major
    for (int idx = t; idx < 8192; idx += 512) {
        int c = idx >> 7;
        int k = idx & 127;
        w2t[k * 64 + c] = W2[idx];
    }
    __syncthreads();

    const int lane = t & 31;
    const int w    = t >> 5;
    const int row  = blockIdx.x * 16 + w;

    // ---- LN1 + leaky ----
    float4 zv = *reinterpret_cast<const float4*>(&g_z1[(size_t)row * 128 + lane * 4]);
    float s  = zv.x + zv.y + zv.z + zv.w;
    float sq = zv.x * zv.x + zv.y * zv.y + zv.z * zv.z + zv.w * zv.w;
    s  = warp_sum32(s);
    sq = warp_sum32(sq);
    float mu   = s * (1.0f / 128.0f);
    float var  = sq * (1.0f / 128.0f) - mu * mu;
    float rstd = rsqrtf(var + LN_EPS);
    float4 gv  = *reinterpret_cast<const float4*>(&g1[lane * 4]);
    float4 bv  = *reinterpret_cast<const float4*>(&be1[lane * 4]);
    h1s[w][lane * 4 + 0] = leaky((zv.x - mu) * rstd * gv.x + bv.x);
    h1s[w][lane * 4 + 1] = leaky((zv.y - mu) * rstd * gv.y + bv.y);
    h1s[w][lane * 4 + 2] = leaky((zv.z - mu) * rstd * gv.z + bv.z);
    h1s[w][lane * 4 + 3] = leaky((zv.w - mu) * rstd * gv.w + bv.w);
    __syncwarp();

    // ---- GEMM2: 2 cols per lane ----
    float z2a = b2[lane];
    float z2b = b2[lane + 32];
#pragma unroll 8
    for (int k = 0; k < 128; k++) {
        float hv = h1s[w][k];
        z2a += hv * w2t[k * 64 + lane];
        z2b += hv * w2t[k * 64 + lane + 32];
    }
    // ---- LN2 + leaky ----
    float s2  = warp_sum32(z2a + z2b);
    float sq2 = warp_sum32(z2a * z2a + z2b * z2b);
    float mu2   = s2 * (1.0f / 64.0f);
    float var2  = sq2 * (1.0f / 64.0f) - mu2 * mu2;
    float rstd2 = rsqrtf(var2 + LN_EPS);
    g_h2[(size_t)row * 64 + lane]      = leaky((z2a - mu2) * rstd2 * g2[lane] + be2[lane]);
    g_h2[(size_t)row * 64 + lane + 32] = leaky((z2b - mu2) * rstd2 * g2[lane + 32] + be2[lane + 32]);
}

// =====================================================================
// Kernel 2b: z3 = h2@W3^T + b3 ; h3 = leaky(LN(z3)) ; M = h3 @ T
// one warp per row, 16 warps/block, grid 128
// =====================================================================
__global__ __launch_bounds__(512) void enc2b_kernel(
    const float* __restrict__ W3, const float* __restrict__ b3,
    const float* __restrict__ g3, const float* __restrict__ be3,
    const float* __restrict__ T) {
    __shared__ float w3t[64 * 32];   // [k][c]
    __shared__ float Ts[32 * 80];    // [k][c] (native layout of T)
    __shared__ float h2s[16][64];
    __shared__ float h3s[16][32];

    const int t = threadIdx.x;
    for (int idx = t; idx < 2048; idx += 512) {
        int c = idx >> 6;
        int k = idx & 63;
        w3t[k * 32 + c] = W3[idx];
    }
    for (int idx = t; idx < 2560; idx += 512) Ts[idx] = T[idx];
    __syncthreads();

    const int lane = t & 31;
    const int w    = t >> 5;
    const int row  = blockIdx.x * 16 + w;

    float2 h2v = *reinterpret_cast<const float2*>(&g_h2[(size_t)row * 64 + lane * 2]);
    h2s[w][lane * 2]     = h2v.x;
    h2s[w][lane * 2 + 1] = h2v.y;
    __syncwarp();

    float z3 = b3[lane];
#pragma unroll 8
    for (int k = 0; k < 64; k++) z3 += h2s[w][k] * w3t[k * 32 + lane];

    float s3  = warp_sum32(z3);
    float sq3 = warp_sum32(z3 * z3);
    float mu3   = s3 * (1.0f / 32.0f);
    float var3  = sq3 * (1.0f / 32.0f) - mu3 * mu3;
    float rstd3 = rsqrtf(var3 + LN_EPS);
    float h3v = leaky((z3 - mu3) * rstd3 * g3[lane] + be3[lane]);
    g_h3[(size_t)row * 32 + lane] = h3v;
    h3s[w][lane] = h3v;
    __syncwarp();

    for (int c = lane; c < 80; c += 32) {
        float m = 0.0f;
#pragma unroll
        for (int k = 0; k < 32; k++) m += h3s[w][k] * Ts[k * 80 + c];
        g_M[(size_t)row * 80 + c] = m;
    }
}

// =====================================================================
// zero the pairwise accumulators
// =====================================================================
__global__ void zero_ob_kernel() {
    int i = blockIdx.x * blockDim.x + threadIdx.x;
    if (i < 2048 * 5) g_ob[i] = 0.0f;
}

// =====================================================================
// Kernel 4: pairwise   ob[i][o] += sum_j exp(-sum_k |M[i,o,k]-M[j,o,k]|)
// grid (4 i-tiles, 5 o, 16 j-splits), 128 threads, 4 i per thread.
// j tile staged NEGATED in smem -> diff via add.f32x2; abs via and.b64.
// =====================================================================
#define PW_THREADS 128
#define PW_I 4
#define PW_J 128
#define ABSM 0x7FFFFFFF7FFFFFFFULL

__global__ __launch_bounds__(PW_THREADS) void pairwise_kernel() {
    __shared__ unsigned long long mjneg[PW_J * 8];

    const int o  = blockIdx.y;
    const int i0 = blockIdx.x * (PW_THREADS * PW_I);
    const int j0 = blockIdx.z * PW_J;
    const int t  = threadIdx.x;

    for (int idx = t; idx < PW_J * 8; idx += PW_THREADS) {
        int jj = idx >> 3;
        int p  = idx & 7;
        float2 v = *reinterpret_cast<const float2*>(
            &g_M[(size_t)(j0 + jj) * 80 + o * 16 + p * 2]);
        union { float2 f; unsigned long long u; } cv;
        cv.f = make_float2(-v.x, -v.y);
        mjneg[jj * 8 + p] = cv.u;
    }

    unsigned long long mi[PW_I][8];
#pragma unroll
    for (int ii = 0; ii < PW_I; ii++) {
        int i = i0 + t + ii * PW_THREADS;
#pragma unroll
        for (int p = 0; p < 8; p++)
            mi[ii][p] = *reinterpret_cast<const unsigned long long*>(
                &g_M[(size_t)i * 80 + o * 16 + p * 2]);
    }
    __syncthreads();

    float es[PW_I] = {0.f, 0.f, 0.f, 0.f};
    for (int jj = 0; jj < PW_J; jj++) {
        unsigned long long mj[8];
#pragma unroll
        for (int p = 0; p < 8; p++) mj[p] = mjneg[jj * 8 + p];
#pragma unroll
        for (int ii = 0; ii < PW_I; ii++) {
            unsigned long long a0 = 0ULL, a1 = 0ULL;
#pragma unroll
            for (int p = 0; p < 8; p += 2) {
                unsigned long long d0 = f32x2_add(mi[ii][p],     mj[p]);
                unsigned long long d1 = f32x2_add(mi[ii][p + 1], mj[p + 1]);
                a0 = f32x2_add(a0, d0 & ABSM);
                a1 = f32x2_add(a1, d1 & ABSM);
            }
            float l1 = hadd2(f32x2_add(a0, a1));
            es[ii] += __expf(-l1);
        }
    }
#pragma unroll
    for (int ii = 0; ii < PW_I; ii++) {
        int i = i0 + t + ii * PW_THREADS;
        atomicAdd(&g_ob[i * 5 + o], es[ii]);
    }
}

// =====================================================================
// Kernel 5: out[i] = bf + Wf[0:32].h3[i] + Wf[32:37].(ob[i]-1)
// =====================================================================
__global__ void final_kernel(const float* __restrict__ Wf,
                             const float* __restrict__ bf,
                             float* __restrict__ out) {
    int i = blockIdx.x * blockDim.x + threadIdx.x;
    if (i >= 2048) return;
    float s = bf[0];
#pragma unroll
    for (int c = 0; c < 32; c++) s += g_h3[(size_t)i * 32 + c] * Wf[c];
#pragma unroll
    for (int oo = 0; oo < 5; oo++) s += (g_ob[i * 5 + oo] - 1.0f) * Wf[32 + oo];
    out[i] = s;
}

// =====================================================================
extern "C" void kernel_launch(void* const* d_in, const int* in_sizes, int n_in,
                              void* d_out, int out_size) {
    (void)in_sizes; (void)n_in; (void)out_size;
    const float* x   = (const float*)d_in[0];
    const float* W1  = (const float*)d_in[1];
    const float* b1  = (const float*)d_in[2];
    const float* g1  = (const float*)d_in[3];
    const float* be1 = (const float*)d_in[4];
    const float* W2  = (const float*)d_in[5];
    const float* b2  = (const float*)d_in[6];
    const float* g2  = (const float*)d_in[7];
    const float* be2 = (const float*)d_in[8];
    const float* W3  = (const float*)d_in[9];
    const float* b3  = (const float*)d_in[10];
    const float* g3  = (const float*)d_in[11];
    const float* be3 = (const float*)d_in[12];
    const float* T   = (const float*)d_in[13];
    const float* Wf  = (const float*)d_in[14];
    const float* bf  = (const float*)d_in[15];
    float* out = (float*)d_out;

    gemm1_kernel<<<dim3(64, 2), 128>>>(x, W1, b1);
    enc2a_kernel<<<128, 512>>>(g1, be1, W2, b2, g2, be2);
    enc2b_kernel<<<128, 512>>>(W3, b3, g3, be3, T);
    zero_ob_kernel<<<10, 1024>>>();
    pairwise_kernel<<<dim3(4, 5, 16), PW_THREADS>>>();
    final_kernel<<<8, 256>>>(Wf, bf, out);
}

// round 2
// speedup vs baseline: 1.2408x; 1.2408x over previous
#include <cuda_runtime.h>
#include <cstdint>

#define LN_EPS 1e-5f
#define NEG_SLOPE 0.2f

// ---------------- scratch (no allocations allowed) ----------------
__device__ float g_z1[2048 * 128];   // x@W1^T + b1
__device__ float g_h2[2048 * 64];    // after LN2+leaky
__device__ float g_h3[2048 * 32];    // after LN3+leaky
__device__ float g_M [2048 * 80];    // h3 @ T
__device__ float g_ob[2048 * 5];     // pairwise accumulators

// ---------------- f32x2 helpers ----------------
__device__ __forceinline__ unsigned long long f32x2_fma(unsigned long long a,
                                                        unsigned long long b,
                                                        unsigned long long c) {
    unsigned long long d;
    asm("fma.rn.f32x2 %0, %1, %2, %3;" : "=l"(d) : "l"(a), "l"(b), "l"(c));
    return d;
}
__device__ __forceinline__ unsigned long long f32x2_add(unsigned long long a,
                                                        unsigned long long b) {
    unsigned long long d;
    asm("add.rn.f32x2 %0, %1, %2;" : "=l"(d) : "l"(a), "l"(b));
    return d;
}
__device__ __forceinline__ float hadd2(unsigned long long a) {
    union { unsigned long long u; float2 f; } c; c.u = a;
    return c.f.x + c.f.y;
}
__device__ __forceinline__ float warp_sum32(float v) {
    v += __shfl_xor_sync(0xffffffffu, v, 16);
    v += __shfl_xor_sync(0xffffffffu, v, 8);
    v += __shfl_xor_sync(0xffffffffu, v, 4);
    v += __shfl_xor_sync(0xffffffffu, v, 2);
    v += __shfl_xor_sync(0xffffffffu, v, 1);
    return v;
}
__device__ __forceinline__ float leaky(float v) {
    return v >= 0.0f ? v : NEG_SLOPE * v;
}

// =====================================================================
// Kernel 1: z1 = x @ W1^T + b1.   M=2048, N=128, K=1024.
// Tile 32x64, BK=32, 256 threads (16x16), thread tile 2x4, packed-k f32x2.
// grid (64, 2)  -> 128 blocks x 8 warps = 1024 warps
// =====================================================================
__global__ __launch_bounds__(256) void gemm1_kernel(
    const float* __restrict__ x, const float* __restrict__ W1,
    const float* __restrict__ b1) {
    __shared__ unsigned long long xs[16 * 32];   // [kp][row]
    __shared__ unsigned long long ws[16 * 64];   // [kp][col]

    const int t  = threadIdx.x;
    const int tx = t & 15;          // col group (16)
    const int ty = t >> 4;          // row group (16)
    const int i0 = blockIdx.x * 32;
    const int j0 = blockIdx.y * 64;

    unsigned long long acc[2][4];
#pragma unroll
    for (int r = 0; r < 2; r++)
#pragma unroll
        for (int c = 0; c < 4; c++) acc[r][c] = 0ULL;

    for (int kc = 0; kc < 1024; kc += 32) {
        // load x tile: 32 rows x 32 k = 256 float4, 1 per thread
        {
            int row = t >> 3;
            int kq  = t & 7;
            float4 v = *reinterpret_cast<const float4*>(
                &x[(size_t)(i0 + row) * 1024 + kc + kq * 4]);
            union { float2 f; unsigned long long u; } p0, p1;
            p0.f = make_float2(v.x, v.y);
            p1.f = make_float2(v.z, v.w);
            xs[(2 * kq) * 32 + row]     = p0.u;
            xs[(2 * kq + 1) * 32 + row] = p1.u;
        }
        // load W tile: 64 cols x 32 k = 512 float4, 2 per thread
#pragma unroll
        for (int u = 0; u < 2; u++) {
            int fi   = t + 256 * u;
            int wrow = fi >> 3;
            int kq   = fi & 7;
            float4 v = *reinterpret_cast<const float4*>(
                &W1[(size_t)(j0 + wrow) * 1024 + kc + kq * 4]);
            union { float2 f; unsigned long long u; } p0, p1;
            p0.f = make_float2(v.x, v.y);
            p1.f = make_float2(v.z, v.w);
            ws[(2 * kq) * 64 + wrow]     = p0.u;
            ws[(2 * kq + 1) * 64 + wrow] = p1.u;
        }
        __syncthreads();

#pragma unroll
        for (int kp = 0; kp < 16; kp++) {
            unsigned long long a2[2], b2[4];
#pragma unroll
            for (int r = 0; r < 2; r++) a2[r] = xs[kp * 32 + ty + 16 * r];
#pragma unroll
            for (int c = 0; c < 4; c++) b2[c] = ws[kp * 64 + tx + 16 * c];
#pragma unroll
            for (int r = 0; r < 2; r++)
#pragma unroll
                for (int c = 0; c < 4; c++)
                    acc[r][c] = f32x2_fma(a2[r], b2[c], acc[r][c]);
        }
        __syncthreads();
    }

    float bias[4];
#pragma unroll
    for (int c = 0; c < 4; c++) bias[c] = b1[j0 + tx + 16 * c];
#pragma unroll
    for (int r = 0; r < 2; r++) {
        int row = i0 + ty + 16 * r;
#pragma unroll
        for (int c = 0; c < 4; c++) {
            int col = j0 + tx + 16 * c;
            g_z1[(size_t)row * 128 + col] = hadd2(acc[r][c]) + bias[c];
        }
    }
}

// =====================================================================
// Kernel 2a: h1 = leaky(LN(z1)) ; z2 = h1@W2^T + b2 ; h2 = leaky(LN(z2))
// one warp per row, 16 warps/block, grid 128
// =====================================================================
__global__ __launch_bounds__(512) void enc2a_kernel(
    const float* __restrict__ g1, const float* __restrict__ be1,
    const float* __restrict__ W2, const float* __restrict__ b2,
    const float* __restrict__ g2, const float* __restrict__ be2) {
    __shared__ float w2t[128 * 64];      // [k][c]
    __shared__ float h1s[16][128];

    const int t = threadIdx.x;
    // load W2 transposed: W2 is [64][128] row-major
    for (int idx = t; idx < 8192; idx += 512) {
        int c = idx >> 7;
        int k = idx & 127;
        w2t[k * 64 + c] = W2[idx];
    }
    __syncthreads();

    const int lane = t & 31;
    const int w    = t >> 5;
    const int row  = blockIdx.x * 16 + w;

    // ---- LN1 + leaky ----
    float4 zv = *reinterpret_cast<const float4*>(&g_z1[(size_t)row * 128 + lane * 4]);
    float s  = zv.x + zv.y + zv.z + zv.w;
    float sq = zv.x * zv.x + zv.y * zv.y + zv.z * zv.z + zv.w * zv.w;
    s  = warp_sum32(s);
    sq = warp_sum32(sq);
    float mu   = s * (1.0f / 128.0f);
    float var  = sq * (1.0f / 128.0f) - mu * mu;
    float rstd = rsqrtf(var + LN_EPS);
    float4 gv  = *reinterpret_cast<const float4*>(&g1[lane * 4]);
    float4 bv  = *reinterpret_cast<const float4*>(&be1[lane * 4]);
    h1s[w][lane * 4 + 0] = leaky((zv.x - mu) * rstd * gv.x + bv.x);
    h1s[w][lane * 4 + 1] = leaky((zv.y - mu) * rstd * gv.y + bv.y);
    h1s[w][lane * 4 + 2] = leaky((zv.z - mu) * rstd * gv.z + bv.z);
    h1s[w][lane * 4 + 3] = leaky((zv.w - mu) * rstd * gv.w + bv.w);
    __syncwarp();

    // ---- GEMM2: 2 cols per lane ----
    float z2a = b2[lane];
    float z2b = b2[lane + 32];
#pragma unroll 8
    for (int k = 0; k < 128; k++) {
        float hv = h1s[w][k];
        z2a += hv * w2t[k * 64 + lane];
        z2b += hv * w2t[k * 64 + lane + 32];
    }
    // ---- LN2 + leaky ----
    float s2  = warp_sum32(z2a + z2b);
    float sq2 = warp_sum32(z2a * z2a + z2b * z2b);
    float mu2   = s2 * (1.0f / 64.0f);
    float var2  = sq2 * (1.0f / 64.0f) - mu2 * mu2;
    float rstd2 = rsqrtf(var2 + LN_EPS);
    g_h2[(size_t)row * 64 + lane]      = leaky((z2a - mu2) * rstd2 * g2[lane] + be2[lane]);
    g_h2[(size_t)row * 64 + lane + 32] = leaky((z2b - mu2) * rstd2 * g2[lane + 32] + be2[lane + 32]);
}

// =====================================================================
// Kernel 2b: z3 = h2@W3^T + b3 ; h3 = leaky(LN(z3)) ; M = h3 @ T
// Also zeroes g_ob (each of 128 blocks zeroes an 80-element slice).
// one warp per row, 16 warps/block, grid 128
// =====================================================================
__global__ __launch_bounds__(512) void enc2b_kernel(
    const float* __restrict__ W3, const float* __restrict__ b3,
    const float* __restrict__ g3, const float* __restrict__ be3,
    const float* __restrict__ T) {
    __shared__ float w3t[64 * 32];   // [k][c]
    __shared__ float Ts[32 * 80];    // [k][c] (native layout of T)
    __shared__ float h2s[16][64];
    __shared__ float h3s[16][32];

    const int t = threadIdx.x;
    // zero g_ob slice (2048*5 / 128 blocks = 80 per block)
    if (t < 80) g_ob[blockIdx.x * 80 + t] = 0.0f;

    for (int idx = t; idx < 2048; idx += 512) {
        int c = idx >> 6;
        int k = idx & 63;
        w3t[k * 32 + c] = W3[idx];
    }
    for (int idx = t; idx < 2560; idx += 512) Ts[idx] = T[idx];
    __syncthreads();

    const int lane = t & 31;
    const int w    = t >> 5;
    const int row  = blockIdx.x * 16 + w;

    float2 h2v = *reinterpret_cast<const float2*>(&g_h2[(size_t)row * 64 + lane * 2]);
    h2s[w][lane * 2]     = h2v.x;
    h2s[w][lane * 2 + 1] = h2v.y;
    __syncwarp();

    float z3 = b3[lane];
#pragma unroll 8
    for (int k = 0; k < 64; k++) z3 += h2s[w][k] * w3t[k * 32 + lane];

    float s3  = warp_sum32(z3);
    float sq3 = warp_sum32(z3 * z3);
    float mu3   = s3 * (1.0f / 32.0f);
    float var3  = sq3 * (1.0f / 32.0f) - mu3 * mu3;
    float rstd3 = rsqrtf(var3 + LN_EPS);
    float h3v = leaky((z3 - mu3) * rstd3 * g3[lane] + be3[lane]);
    g_h3[(size_t)row * 32 + lane] = h3v;
    h3s[w][lane] = h3v;
    __syncwarp();

    for (int c = lane; c < 80; c += 32) {
        float m = 0.0f;
#pragma unroll
        for (int k = 0; k < 32; k++) m += h3s[w][k] * Ts[k * 80 + c];
        g_M[(size_t)row * 80 + c] = m;
    }
}

// =====================================================================
// Kernel 4: pairwise   ob[i][o] += sum_j exp(-sum_k |M[i,o,k]-M[j,o,k]|)
// grid (4 i-tiles, 5 o, 32 j-splits), 128 threads, 4 i per thread.
// 2560 warps total (~17/SM) for latency hiding.
// j tile staged NEGATED in smem -> diff via add.f32x2; abs via and.b64.
// =====================================================================
#define PW_THREADS 128
#define PW_I 4
#define PW_J 64
#define ABSM 0x7FFFFFFF7FFFFFFFULL

__global__ __launch_bounds__(PW_THREADS) void pairwise_kernel() {
    __shared__ unsigned long long mjneg[PW_J * 8];

    const int o  = blockIdx.y;
    const int i0 = blockIdx.x * (PW_THREADS * PW_I);
    const int j0 = blockIdx.z * PW_J;
    const int t  = threadIdx.x;

    for (int idx = t; idx < PW_J * 8; idx += PW_THREADS) {
        int jj = idx >> 3;
        int p  = idx & 7;
        float2 v = *reinterpret_cast<const float2*>(
            &g_M[(size_t)(j0 + jj) * 80 + o * 16 + p * 2]);
        union { float2 f; unsigned long long u; } cv;
        cv.f = make_float2(-v.x, -v.y);
        mjneg[jj * 8 + p] = cv.u;
    }

    unsigned long long mi[PW_I][8];
#pragma unroll
    for (int ii = 0; ii < PW_I; ii++) {
        int i = i0 + t + ii * PW_THREADS;
#pragma unroll
        for (int p = 0; p < 8; p++)
            mi[ii][p] = *reinterpret_cast<const unsigned long long*>(
                &g_M[(size_t)i * 80 + o * 16 + p * 2]);
    }
    __syncthreads();

    float es[PW_I] = {0.f, 0.f, 0.f, 0.f};
    for (int jj = 0; jj < PW_J; jj++) {
        unsigned long long mj[8];
#pragma unroll
        for (int p = 0; p < 8; p++) mj[p] = mjneg[jj * 8 + p];
#pragma unroll
        for (int ii = 0; ii < PW_I; ii++) {
            unsigned long long a0 = 0ULL, a1 = 0ULL;
#pragma unroll
            for (int p = 0; p < 8; p += 2) {
                unsigned long long d0 = f32x2_add(mi[ii][p],     mj[p]);
                unsigned long long d1 = f32x2_add(mi[ii][p + 1], mj[p + 1]);
                a0 = f32x2_add(a0, d0 & ABSM);
                a1 = f32x2_add(a1, d1 & ABSM);
            }
            float l1 = hadd2(f32x2_add(a0, a1));
            es[ii] += __expf(-l1);
        }
    }
#pragma unroll
    for (int ii = 0; ii < PW_I; ii++) {
        int i = i0 + t + ii * PW_THREADS;
        atomicAdd(&g_ob[i * 5 + o], es[ii]);
    }
}

// =====================================================================
// Kernel 5: out[i] = bf + Wf[0:32].h3[i] + Wf[32:37].(ob[i]-1)
// =====================================================================
__global__ void final_kernel(const float* __restrict__ Wf,
                             const float* __restrict__ bf,
                             float* __restrict__ out) {
    int i = blockIdx.x * blockDim.x + threadIdx.x;
    if (i >= 2048) return;
    float s = bf[0];
#pragma unroll
    for (int c = 0; c < 32; c++) s += g_h3[(size_t)i * 32 + c] * Wf[c];
#pragma unroll
    for (int oo = 0; oo < 5; oo++) s += (g_ob[i * 5 + oo] - 1.0f) * Wf[32 + oo];
    out[i] = s;
}

// =====================================================================
extern "C" void kernel_launch(void* const* d_in, const int* in_sizes, int n_in,
                              void* d_out, int out_size) {
    (void)in_sizes; (void)n_in; (void)out_size;
    const float* x   = (const float*)d_in[0];
    const float* W1  = (const float*)d_in[1];
    const float* b1  = (const float*)d_in[2];
    const float* g1  = (const float*)d_in[3];
    const float* be1 = (const float*)d_in[4];
    const float* W2  = (const float*)d_in[5];
    const float* b2  = (const float*)d_in[6];
    const float* g2  = (const float*)d_in[7];
    const float* be2 = (const float*)d_in[8];
    const float* W3  = (const float*)d_in[9];
    const float* b3  = (const float*)d_in[10];
    const float* g3  = (const float*)d_in[11];
    const float* be3 = (const float*)d_in[12];
    const float* T   = (const float*)d_in[13];
    const float* Wf  = (const float*)d_in[14];
    const float* bf  = (const float*)d_in[15];
    float* out = (float*)d_out;

    gemm1_kernel<<<dim3(64, 2), 256>>>(x, W1, b1);
    enc2a_kernel<<<128, 512>>>(g1, be1, W2, b2, g2, be2);
    enc2b_kernel<<<128, 512>>>(W3, b3, g3, be3, T);
    pairwise_kernel<<<dim3(4, 5, 32), PW_THREADS>>>();
    final_kernel<<<8, 256>>>(Wf, bf, out);
}

// round 3
// speedup vs baseline: 1.3088x; 1.0548x over previous
#include <cuda_runtime.h>
#include <cstdint>

#define LN_EPS 1e-5f
#define NEG_SLOPE 0.2f
#define LOG2E 1.4426950408889634f

// ---------------- scratch (no allocations allowed) ----------------
__device__ float g_z1[2048 * 128];   // x@W1^T + b1
__device__ float g_h2[2048 * 64];    // after LN2+leaky
__device__ float g_h3[2048 * 32];    // after LN3+leaky
__device__ float g_M [2048 * 80];    // (h3 @ T) * log2(e)  [pre-scaled]
__device__ float g_ob[2048 * 5];     // pairwise accumulators

// ---------------- f32x2 helpers ----------------
__device__ __forceinline__ unsigned long long f32x2_fma(unsigned long long a,
                                                        unsigned long long b,
                                                        unsigned long long c) {
    unsigned long long d;
    asm("fma.rn.f32x2 %0, %1, %2, %3;" : "=l"(d) : "l"(a), "l"(b), "l"(c));
    return d;
}
__device__ __forceinline__ unsigned long long f32x2_add(unsigned long long a,
                                                        unsigned long long b) {
    unsigned long long d;
    asm("add.rn.f32x2 %0, %1, %2;" : "=l"(d) : "l"(a), "l"(b));
    return d;
}
__device__ __forceinline__ float hadd2(unsigned long long a) {
    union { unsigned long long u; float2 f; } c; c.u = a;
    return c.f.x + c.f.y;
}
__device__ __forceinline__ float warp_sum32(float v) {
    v += __shfl_xor_sync(0xffffffffu, v, 16);
    v += __shfl_xor_sync(0xffffffffu, v, 8);
    v += __shfl_xor_sync(0xffffffffu, v, 4);
    v += __shfl_xor_sync(0xffffffffu, v, 2);
    v += __shfl_xor_sync(0xffffffffu, v, 1);
    return v;
}
__device__ __forceinline__ float leaky(float v) {
    return v >= 0.0f ? v : NEG_SLOPE * v;
}
__device__ __forceinline__ float ex2_approx(float v) {
    float r;
    asm("ex2.approx.f32 %0, %1;" : "=f"(r) : "f"(v));
    return r;
}

// =====================================================================
// Kernel 1: z1 = x @ W1^T + b1.   M=2048, N=128, K=1024.
// Tile 32x64, BK=32, 256 threads (16x16), thread tile 2x4, packed-k f32x2.
// grid (64, 2)
// =====================================================================
__global__ __launch_bounds__(256) void gemm1_kernel(
    const float* __restrict__ x, const float* __restrict__ W1,
    const float* __restrict__ b1) {
    __shared__ unsigned long long xs[16 * 32];   // [kp][row]
    __shared__ unsigned long long ws[16 * 64];   // [kp][col]

    const int t  = threadIdx.x;
    const int tx = t & 15;          // col group (16)
    const int ty = t >> 4;          // row group (16)
    const int i0 = blockIdx.x * 32;
    const int j0 = blockIdx.y * 64;

    unsigned long long acc[2][4];
#pragma unroll
    for (int r = 0; r < 2; r++)
#pragma unroll
        for (int c = 0; c < 4; c++) acc[r][c] = 0ULL;

    for (int kc = 0; kc < 1024; kc += 32) {
        {
            int row = t >> 3;
            int kq  = t & 7;
            float4 v = *reinterpret_cast<const float4*>(
                &x[(size_t)(i0 + row) * 1024 + kc + kq * 4]);
            union { float2 f; unsigned long long u; } p0, p1;
            p0.f = make_float2(v.x, v.y);
            p1.f = make_float2(v.z, v.w);
            xs[(2 * kq) * 32 + row]     = p0.u;
            xs[(2 * kq + 1) * 32 + row] = p1.u;
        }
#pragma unroll
        for (int u = 0; u < 2; u++) {
            int fi   = t + 256 * u;
            int wrow = fi >> 3;
            int kq   = fi & 7;
            float4 v = *reinterpret_cast<const float4*>(
                &W1[(size_t)(j0 + wrow) * 1024 + kc + kq * 4]);
            union { float2 f; unsigned long long u; } p0, p1;
            p0.f = make_float2(v.x, v.y);
            p1.f = make_float2(v.z, v.w);
            ws[(2 * kq) * 64 + wrow]     = p0.u;
            ws[(2 * kq + 1) * 64 + wrow] = p1.u;
        }
        __syncthreads();

#pragma unroll
        for (int kp = 0; kp < 16; kp++) {
            unsigned long long a2[2], b2[4];
#pragma unroll
            for (int r = 0; r < 2; r++) a2[r] = xs[kp * 32 + ty + 16 * r];
#pragma unroll
            for (int c = 0; c < 4; c++) b2[c] = ws[kp * 64 + tx + 16 * c];
#pragma unroll
            for (int r = 0; r < 2; r++)
#pragma unroll
                for (int c = 0; c < 4; c++)
                    acc[r][c] = f32x2_fma(a2[r], b2[c], acc[r][c]);
        }
        __syncthreads();
    }

    float bias[4];
#pragma unroll
    for (int c = 0; c < 4; c++) bias[c] = b1[j0 + tx + 16 * c];
#pragma unroll
    for (int r = 0; r < 2; r++) {
        int row = i0 + ty + 16 * r;
#pragma unroll
        for (int c = 0; c < 4; c++) {
            int col = j0 + tx + 16 * c;
            g_z1[(size_t)row * 128 + col] = hadd2(acc[r][c]) + bias[c];
        }
    }
}

// =====================================================================
// Kernel 2a: h1 = leaky(LN(z1)) ; z2 = h1@W2^T + b2 ; h2 = leaky(LN(z2))
// one warp per row, 16 warps/block, grid 128.
// W2 staged interleaved: w2s[k*64 + lane*2 + {0,1}] = cols {lane, lane+32}
// GEMM2 uses 8 independent accumulator chains (2 outputs x 4 partials).
// =====================================================================
__global__ __launch_bounds__(512) void enc2a_kernel(
    const float* __restrict__ g1, const float* __restrict__ be1,
    const float* __restrict__ W2, const float* __restrict__ b2,
    const float* __restrict__ g2, const float* __restrict__ be2) {
    __shared__ float w2s[128 * 64];      // [k][pair-interleaved cols]
    __shared__ float h1s[16][128];

    const int t = threadIdx.x;
    // W2 is [64][128] row-major; read coalesced, scatter to interleaved smem
    for (int idx = t; idx < 8192; idx += 512) {
        int col = idx >> 7;          // 0..63
        int k   = idx & 127;
        w2s[k * 64 + (col & 31) * 2 + (col >> 5)] = W2[idx];
    }
    __syncthreads();

    const int lane = t & 31;
    const int w    = t >> 5;
    const int row  = blockIdx.x * 16 + w;

    // ---- LN1 + leaky ----
    float4 zv = *reinterpret_cast<const float4*>(&g_z1[(size_t)row * 128 + lane * 4]);
    float s  = zv.x + zv.y + zv.z + zv.w;
    float sq = zv.x * zv.x + zv.y * zv.y + zv.z * zv.z + zv.w * zv.w;
    s  = warp_sum32(s);
    sq = warp_sum32(sq);
    float mu   = s * (1.0f / 128.0f);
    float var  = sq * (1.0f / 128.0f) - mu * mu;
    float rstd = rsqrtf(var + LN_EPS);
    float4 gv  = *reinterpret_cast<const float4*>(&g1[lane * 4]);
    float4 bv  = *reinterpret_cast<const float4*>(&be1[lane * 4]);
    h1s[w][lane * 4 + 0] = leaky((zv.x - mu) * rstd * gv.x + bv.x);
    h1s[w][lane * 4 + 1] = leaky((zv.y - mu) * rstd * gv.y + bv.y);
    h1s[w][lane * 4 + 2] = leaky((zv.z - mu) * rstd * gv.z + bv.z);
    h1s[w][lane * 4 + 3] = leaky((zv.w - mu) * rstd * gv.w + bv.w);
    __syncwarp();

    // ---- GEMM2: 2 cols per lane, 4 partials each ----
    float pa0 = 0.f, pa1 = 0.f, pa2 = 0.f, pa3 = 0.f;
    float pb0 = 0.f, pb1 = 0.f, pb2 = 0.f, pb3 = 0.f;
#pragma unroll
    for (int k4 = 0; k4 < 128; k4 += 4) {
        float4 hv = *reinterpret_cast<const float4*>(&h1s[w][k4]);
        float2 w0 = *reinterpret_cast<const float2*>(&w2s[(k4 + 0) * 64 + lane * 2]);
        float2 w1 = *reinterpret_cast<const float2*>(&w2s[(k4 + 1) * 64 + lane * 2]);
        float2 w2v = *reinterpret_cast<const float2*>(&w2s[(k4 + 2) * 64 + lane * 2]);
        float2 w3 = *reinterpret_cast<const float2*>(&w2s[(k4 + 3) * 64 + lane * 2]);
        pa0 += hv.x * w0.x;  pb0 += hv.x * w0.y;
        pa1 += hv.y * w1.x;  pb1 += hv.y * w1.y;
        pa2 += hv.z * w2v.x; pb2 += hv.z * w2v.y;
        pa3 += hv.w * w3.x;  pb3 += hv.w * w3.y;
    }
    float z2a = (pa0 + pa1) + (pa2 + pa3) + b2[lane];
    float z2b = (pb0 + pb1) + (pb2 + pb3) + b2[lane + 32];

    // ---- LN2 + leaky ----
    float s2  = warp_sum32(z2a + z2b);
    float sq2 = warp_sum32(z2a * z2a + z2b * z2b);
    float mu2   = s2 * (1.0f / 64.0f);
    float var2  = sq2 * (1.0f / 64.0f) - mu2 * mu2;
    float rstd2 = rsqrtf(var2 + LN_EPS);
    g_h2[(size_t)row * 64 + lane]      = leaky((z2a - mu2) * rstd2 * g2[lane] + be2[lane]);
    g_h2[(size_t)row * 64 + lane + 32] = leaky((z2b - mu2) * rstd2 * g2[lane + 32] + be2[lane + 32]);
}

// =====================================================================
// Kernel 2b: z3 = h2@W3^T + b3 ; h3 = leaky(LN(z3)) ; M = (h3 @ T)*log2e
// Also zeroes g_ob. one warp per row, 16 warps/block, grid 128
// =====================================================================
__global__ __launch_bounds__(512) void enc2b_kernel(
    const float* __restrict__ W3, const float* __restrict__ b3,
    const float* __restrict__ g3, const float* __restrict__ be3,
    const float* __restrict__ T) {
    __shared__ float w3t[64 * 32];   // [k][c]
    __shared__ float Ts[32 * 80];    // [k][c]
    __shared__ float h2s[16][64];
    __shared__ float h3s[16][32];

    const int t = threadIdx.x;
    if (t < 80) g_ob[blockIdx.x * 80 + t] = 0.0f;

    for (int idx = t; idx < 2048; idx += 512) {
        int c = idx >> 6;
        int k = idx & 63;
        w3t[k * 32 + c] = W3[idx];
    }
    for (int idx = t; idx < 2560; idx += 512) Ts[idx] = T[idx];
    __syncthreads();

    const int lane = t & 31;
    const int w    = t >> 5;
    const int row  = blockIdx.x * 16 + w;

    float2 h2v = *reinterpret_cast<const float2*>(&g_h2[(size_t)row * 64 + lane * 2]);
    h2s[w][lane * 2]     = h2v.x;
    h2s[w][lane * 2 + 1] = h2v.y;
    __syncwarp();

    float q0 = 0.f, q1 = 0.f, q2 = 0.f, q3 = 0.f;
#pragma unroll
    for (int k = 0; k < 64; k += 4) {
        q0 += h2s[w][k + 0] * w3t[(k + 0) * 32 + lane];
        q1 += h2s[w][k + 1] * w3t[(k + 1) * 32 + lane];
        q2 += h2s[w][k + 2] * w3t[(k + 2) * 32 + lane];
        q3 += h2s[w][k + 3] * w3t[(k + 3) * 32 + lane];
    }
    float z3 = (q0 + q1) + (q2 + q3) + b3[lane];

    float s3  = warp_sum32(z3);
    float sq3 = warp_sum32(z3 * z3);
    float mu3   = s3 * (1.0f / 32.0f);
    float var3  = sq3 * (1.0f / 32.0f) - mu3 * mu3;
    float rstd3 = rsqrtf(var3 + LN_EPS);
    float h3v = leaky((z3 - mu3) * rstd3 * g3[lane] + be3[lane]);
    g_h3[(size_t)row * 32 + lane] = h3v;
    h3s[w][lane] = h3v;
    __syncwarp();

    for (int c = lane; c < 80; c += 32) {
        float m0 = 0.f, m1 = 0.f;
#pragma unroll
        for (int k = 0; k < 32; k += 2) {
            m0 += h3s[w][k]     * Ts[k * 80 + c];
            m1 += h3s[w][k + 1] * Ts[(k + 1) * 80 + c];
        }
        g_M[(size_t)row * 80 + c] = (m0 + m1) * LOG2E;   // pre-scale for ex2
    }
}

// =====================================================================
// Kernel 4: pairwise   ob[i][o] += sum_j exp2(-sum_k |M'[i,o,k]-M'[j,o,k]|)
// (M' pre-scaled by log2e, so exp2 == exp of unscaled l1)
// grid (4 i-tiles, 5 o, 32 j-splits), 256 threads, 2 i per thread.
// 5120 warps (~8.6/SMSP).
// =====================================================================
#define PW_THREADS 256
#define PW_I 2
#define PW_J 64
#define ABSM 0x7FFFFFFF7FFFFFFFULL

__global__ __launch_bounds__(PW_THREADS) void pairwise_kernel() {
    __shared__ unsigned long long mjneg[PW_J * 8];

    const int o  = blockIdx.y;
    const int i0 = blockIdx.x * (PW_THREADS * PW_I);
    const int j0 = blockIdx.z * PW_J;
    const int t  = threadIdx.x;

    for (int idx = t; idx < PW_J * 8; idx += PW_THREADS) {
        int jj = idx >> 3;
        int p  = idx & 7;
        float2 v = *reinterpret_cast<const float2*>(
            &g_M[(size_t)(j0 + jj) * 80 + o * 16 + p * 2]);
        union { float2 f; unsigned long long u; } cv;
        cv.f = make_float2(-v.x, -v.y);
        mjneg[jj * 8 + p] = cv.u;
    }

    unsigned long long mi[PW_I][8];
#pragma unroll
    for (int ii = 0; ii < PW_I; ii++) {
        int i = i0 + t + ii * PW_THREADS;
#pragma unroll
        for (int p = 0; p < 8; p++)
            mi[ii][p] = *reinterpret_cast<const unsigned long long*>(
                &g_M[(size_t)i * 80 + o * 16 + p * 2]);
    }
    __syncthreads();

    float es[PW_I];
#pragma unroll
    for (int ii = 0; ii < PW_I; ii++) es[ii] = 0.f;

    for (int jj = 0; jj < PW_J; jj++) {
        unsigned long long mj[8];
#pragma unroll
        for (int p = 0; p < 8; p++) mj[p] = mjneg[jj * 8 + p];
#pragma unroll
        for (int ii = 0; ii < PW_I; ii++) {
            unsigned long long a0 = 0ULL, a1 = 0ULL;
#pragma unroll
            for (int p = 0; p < 8; p += 2) {
                unsigned long long d0 = f32x2_add(mi[ii][p],     mj[p]);
                unsigned long long d1 = f32x2_add(mi[ii][p + 1], mj[p + 1]);
                a0 = f32x2_add(a0, d0 & ABSM);
                a1 = f32x2_add(a1, d1 & ABSM);
            }
            unsigned long long at = f32x2_add(a0, a1);
            union { unsigned long long u; float2 f; } c; c.u = at;
            float nl1 = -c.f.x - c.f.y;          // single FADD w/ neg modifiers
            es[ii] += ex2_approx(nl1);           // MUFU.EX2
        }
    }
#pragma unroll
    for (int ii = 0; ii < PW_I; ii++) {
        int i = i0 + t + ii * PW_THREADS;
        atomicAdd(&g_ob[i * 5 + o], es[ii]);
    }
}

// =====================================================================
// Kernel 5: out[i] = bf + Wf[0:32].h3[i] + Wf[32:37].(ob[i]-1)
// =====================================================================
__global__ void final_kernel(const float* __restrict__ Wf,
                             const float* __restrict__ bf,
                             float* __restrict__ out) {
    int i = blockIdx.x * blockDim.x + threadIdx.x;
    if (i >= 2048) return;
    float s = bf[0];
#pragma unroll
    for (int c = 0; c < 32; c++) s += g_h3[(size_t)i * 32 + c] * Wf[c];
#pragma unroll
    for (int oo = 0; oo < 5; oo++) s += (g_ob[i * 5 + oo] - 1.0f) * Wf[32 + oo];
    out[i] = s;
}

// =====================================================================
extern "C" void kernel_launch(void* const* d_in, const int* in_sizes, int n_in,
                              void* d_out, int out_size) {
    (void)in_sizes; (void)n_in; (void)out_size;
    const float* x   = (const float*)d_in[0];
    const float* W1  = (const float*)d_in[1];
    const float* b1  = (const float*)d_in[2];
    const float* g1  = (const float*)d_in[3];
    const float* be1 = (const float*)d_in[4];
    const float* W2  = (const float*)d_in[5];
    const float* b2  = (const float*)d_in[6];
    const float* g2  = (const float*)d_in[7];
    const float* be2 = (const float*)d_in[8];
    const float* W3  = (const float*)d_in[9];
    const float* b3  = (const float*)d_in[10];
    const float* g3  = (const float*)d_in[11];
    const float* be3 = (const float*)d_in[12];
    const float* T   = (const float*)d_in[13];
    const float* Wf  = (const float*)d_in[14];
    const float* bf  = (const float*)d_in[15];
    float* out = (float*)d_out;

    gemm1_kernel<<<dim3(64, 2), 256>>>(x, W1, b1);
    enc2a_kernel<<<128, 512>>>(g1, be1, W2, b2, g2, be2);
    enc2b_kernel<<<128, 512>>>(W3, b3, g3, be3, T);
    pairwise_kernel<<<dim3(4, 5, 32), PW_THREADS>>>();
    final_kernel<<<8, 256>>>(Wf, bf, out);
}